// round 16
// baseline (speedup 1.0000x reference)
#include <cuda_runtime.h>
#include <cuda_fp16.h>
#include <cstdint>

#define NEXP  8
#define BATCH 4096
#define GS    4

// ---------------- device scratch (no allocations allowed) ----------------
__device__ float g_gs1[NEXP * 32];
__device__ float g_gb1[NEXP * 32];
__device__ float g_gs2[NEXP * 64];
__device__ float g_gb2[NEXP * 64];
__device__ int   g_expid[2 * BATCH];
__device__ float g_gatev[2 * BATCH];
// W2 fp16 pre-padded to smem row layout: [e][tap][oc64][ic0..31 + 8 pad halfs] (pad stays 0)
__device__ __half g_w2s[NEXP * 9 * 64 * 40];
// W1 in fp16, tap-major: [e][tap][oc32][k8: ic0..2, 0...]  (zero-padded; .bss zero-init)
__device__ __half g_w1h[NEXP * 9 * 32 * 8];
// fc weights in fp16: [e][o10][j4096]
__device__ __half g_fcwh[NEXP * 10 * 4096];

// ---------------- smem / mma helpers ----------------
static __device__ __forceinline__ uint32_t smem_u32(const void* p) {
    uint32_t a;
    asm("{ .reg .u64 t; cvta.to.shared.u64 t, %1; cvt.u32.u64 %0, t; }" : "=r"(a) : "l"(p));
    return a;
}
static __device__ __forceinline__ void sts32(uint32_t a, uint32_t v) {
    asm volatile("st.shared.b32 [%0], %1;" :: "r"(a), "r"(v) : "memory");
}
static __device__ __forceinline__ void sts128(uint32_t a, uint4 v) {
    asm volatile("st.shared.v4.b32 [%0], {%1,%2,%3,%4};" :: "r"(a), "r"(v.x), "r"(v.y), "r"(v.z), "r"(v.w) : "memory");
}
static __device__ __forceinline__ void cpa16(uint32_t smem, const void* gmem) {
    asm volatile("cp.async.cg.shared.global [%0], [%1], 16;" :: "r"(smem), "l"(gmem) : "memory");
}
static __device__ __forceinline__ void ldm4(uint32_t* r, uint32_t addr) {
    asm volatile("ldmatrix.sync.aligned.m8n8.x4.shared.b16 {%0,%1,%2,%3}, [%4];"
                 : "=r"(r[0]), "=r"(r[1]), "=r"(r[2]), "=r"(r[3]) : "r"(addr));
}
static __device__ __forceinline__ void mma16816(float* d, const uint32_t* a, const uint32_t* b) {
    asm volatile("mma.sync.aligned.m16n8k16.row.col.f32.f16.f16.f32 "
                 "{%0,%1,%2,%3}, {%4,%5,%6,%7}, {%8,%9}, {%0,%1,%2,%3};"
                 : "+f"(d[0]), "+f"(d[1]), "+f"(d[2]), "+f"(d[3])
                 : "r"(a[0]), "r"(a[1]), "r"(a[2]), "r"(a[3]), "r"(b[0]), "r"(b[1]));
}
static __device__ __forceinline__ void mma1688(float* d, uint32_t a0, uint32_t a1, uint32_t b0) {
    asm volatile("mma.sync.aligned.m16n8k8.row.col.f32.f16.f16.f32 "
                 "{%0,%1,%2,%3}, {%4,%5}, {%6}, {%0,%1,%2,%3};"
                 : "+f"(d[0]), "+f"(d[1]), "+f"(d[2]), "+f"(d[3])
                 : "r"(a0), "r"(a1), "r"(b0));
}
static __device__ __forceinline__ uint32_t h2pack(float a, float b) {
    return ((uint32_t)__half_as_ushort(__float2half_rn(b)) << 16)
         | (uint32_t)__half_as_ushort(__float2half_rn(a));
}

// ---------------- fused prep: BN fold + W1/W2/fcw fp16 conversion ----------------
__global__ void prep_kernel(const float* __restrict__ w1, const float* __restrict__ w2,
                            const float* __restrict__ fcw,
                            const float* __restrict__ b1, const float* __restrict__ g1,
                            const float* __restrict__ be1, const float* __restrict__ rm1,
                            const float* __restrict__ rv1,
                            const float* __restrict__ b2, const float* __restrict__ g2,
                            const float* __restrict__ be2, const float* __restrict__ rm2,
                            const float* __restrict__ rv2) {
    int idx = blockIdx.x * 256 + threadIdx.x;
    if (idx < NEXP * 32) {
        float s = g1[idx] / sqrtf(rv1[idx] + 1e-5f);
        g_gs1[idx] = s;
        g_gb1[idx] = (b1[idx] - rm1[idx]) * s + be1[idx];
    }
    if (idx < NEXP * 64) {
        float s = g2[idx] / sqrtf(rv2[idx] + 1e-5f);
        g_gs2[idx] = s;
        g_gb2[idx] = (b2[idx] - rm2[idx]) * s + be2[idx];
    }
    if (idx < NEXP * 9 * 32 * 3) {
        int ic  = idx % 3;
        int t   = idx / 3;
        int oc  = t % 32;  t /= 32;
        int tap = t % 9;
        int e   = t / 9;
        float v = w1[(((size_t)e * 32 + oc) * 3 + ic) * 9 + tap];
        g_w1h[((size_t)(e * 9 + tap) * 32 + oc) * 8 + ic] = __float2half_rn(v);
    }
    if (idx < NEXP * 9 * 64 * 32) {
        int ic  = idx & 31;
        int oc  = (idx >> 5) & 63;
        int r   = idx >> 11;
        int tap = r % 9;
        int e   = r / 9;
        float w = w2[(((size_t)e * 64 + oc) * 32 + ic) * 9 + tap];
        g_w2s[((size_t)(e * 9 + tap) * 64 + oc) * 40 + ic] = __float2half_rn(w);
    }
    if (idx < NEXP * 10 * 4096) {
        g_fcwh[idx] = __float2half_rn(fcw[idx]);
    }
}

// ---------------- gating: 4 samples per block, float4 both sides ----------------
__global__ void __launch_bounds__(256) gate_kernel(const float* __restrict__ x,
                                                   const float* __restrict__ wg) {
    __shared__ float red[8][GS * 8];
    int b0 = blockIdx.x * GS;
    int t  = threadIdx.x;            // 256 threads
    int lane = t & 31, w = t >> 5;
    const float4* xb4 = (const float4*)(x + (size_t)b0 * 3072);

    float p[GS][8];
#pragma unroll
    for (int s = 0; s < GS; s++)
#pragma unroll
        for (int i = 0; i < 8; i++) p[s][i] = 0.f;

#pragma unroll
    for (int it = 0; it < 3; it++) {
        int j4 = t + it * 256;       // float4 index 0..767
        const float4* w4 = (const float4*)(wg + (size_t)j4 * 32);
        float4 xv[GS];
#pragma unroll
        for (int s = 0; s < GS; s++) xv[s] = xb4[s * 768 + j4];
#pragma unroll
        for (int k = 0; k < 4; k++) {
            float4 w0 = w4[2 * k], w1 = w4[2 * k + 1];
#pragma unroll
            for (int s = 0; s < GS; s++) {
                float xk = (k == 0) ? xv[s].x : (k == 1) ? xv[s].y : (k == 2) ? xv[s].z : xv[s].w;
                p[s][0] += xk * w0.x; p[s][1] += xk * w0.y; p[s][2] += xk * w0.z; p[s][3] += xk * w0.w;
                p[s][4] += xk * w1.x; p[s][5] += xk * w1.y; p[s][6] += xk * w1.z; p[s][7] += xk * w1.w;
            }
        }
    }
#pragma unroll
    for (int off = 16; off; off >>= 1)
#pragma unroll
        for (int s = 0; s < GS; s++)
#pragma unroll
            for (int i = 0; i < 8; i++) p[s][i] += __shfl_xor_sync(0xffffffffu, p[s][i], off);
    if (lane == 0)
#pragma unroll
        for (int s = 0; s < GS; s++)
#pragma unroll
            for (int i = 0; i < 8; i++) red[w][s * 8 + i] = p[s][i];
    __syncthreads();
    if (t < GS * 8) {
        float sum = 0.f;
#pragma unroll
        for (int ww = 0; ww < 8; ww++) sum += red[ww][t];
        red[0][t] = sum;
    }
    __syncthreads();
    if (t < GS) {
        float lg[8];
#pragma unroll
        for (int i = 0; i < 8; i++) lg[i] = red[0][t * 8 + i];
        // top-2, first-occurrence tie order (matches jax.lax.top_k)
        int i0 = 0;
#pragma unroll
        for (int e = 1; e < 8; e++) if (lg[e] > lg[i0]) i0 = e;
        int i1 = -1;
#pragma unroll
        for (int e = 0; e < 8; e++) {
            if (e == i0) continue;
            if (i1 < 0 || lg[e] > lg[i1]) i1 = e;
        }
        float t1  = expf(lg[i1] - lg[i0]);     // <= 1
        float inv = 1.f / (1.f + t1);
        int b = b0 + t;
        g_expid[2 * b]     = i0;
        g_gatev[2 * b]     = inv;
        g_expid[2 * b + 1] = i1;
        g_gatev[2 * b + 1] = t1 * inv;
    }
}

// ---------------- fused sample kernel: one block = one sample, both experts ----------------
// smem layout (bytes):
//  A    [0, 25920):        324 rows x 80B (conv2 A: [s][32 oc fp16] + 16B pad)
//  B2   [25920, 72000):    9 taps x 64 rows x 80B (conv2 weights, cp.async, reused per expert)
//  XH   [72000, 90496):    conv1 input fp16, 34x34 grid x 16B rows (staged ONCE)
//  W1H  [90496, 99712):    2 experts x 9 taps x 32 rows x 16B
//  H2S  [99712, 107904):   h2 pooled activations fp16[4096]
//  sS1  [107904,+256) sQ1 [108160,+256) sS2 [108416,+512) sQ2 [108928,+512)
//  red  [109440,+320) oo [109760,+80)
#define A_STRIDE 80
#define B2_OFF   25920
#define XH_OFF   72000
#define W1H_OFF  90496
#define H2S_OFF  99712
#define SS1_OFF  107904
#define SQ1_OFF  108160
#define SS2_OFF  108416
#define SQ2_OFF  108928
#define RED_OFF  109440
#define OO_OFF   109760
#define SMEM_BYTES 109840

static __device__ __forceinline__ void issue_b2(uint32_t B2u, int e, int tid) {
    const uint4* w2src = (const uint4*)(g_w2s) + (size_t)e * 2880;  // 46080 B
#pragma unroll
    for (int j = 0; j < 11; j++) {
        int i = tid + j * 256;
        cpa16(B2u + (uint32_t)(i * 16), w2src + i);
    }
    {
        int i = tid + 11 * 256;
        if (i < 2880) cpa16(B2u + (uint32_t)(i * 16), w2src + i);
    }
    asm volatile("cp.async.commit_group;" ::: "memory");
}

__global__ void __launch_bounds__(256, 2) sample_kernel(
    const float* __restrict__ x, const float* __restrict__ fcb,
    float* __restrict__ out) {
    extern __shared__ __align__(128) char sb[];
    uint32_t Au   = smem_u32(sb);
    uint32_t B2u  = Au + B2_OFF;
    uint32_t XHu  = Au + XH_OFF;
    uint32_t W1Hu = Au + W1H_OFF;
    float* sS1  = (float*)(sb + SS1_OFF);
    float* sQ1  = (float*)(sb + SQ1_OFF);
    float* sS2  = (float*)(sb + SS2_OFF);
    float* sQ2  = (float*)(sb + SQ2_OFF);
    float* redm = (float*)(sb + RED_OFF);
    float* oo   = (float*)(sb + OO_OFF);
    __half* h2h = (__half*)(sb + H2S_OFF);

    int b    = blockIdx.x;
    int e0   = g_expid[2 * b];
    int e1   = g_expid[2 * b + 1];
    int tid  = threadIdx.x;
    int lane = tid & 31;
    int w    = tid >> 5;

    // ---- prefetch B2(e0) ----
    issue_b2(B2u, e0, tid);

    // ---- phase 0: zero A halo + XH halo; load BN consts for both experts ----
    for (int i = tid; i < 1620; i += 256) sts128(Au + i * 16, make_uint4(0, 0, 0, 0));
    for (int i = tid; i < 1156; i += 256) sts128(XHu + i * 16, make_uint4(0, 0, 0, 0));
    if (tid < 64) {
        int ee = tid >> 5, i = tid & 31;
        int e = ee ? e1 : e0;
        sS1[tid] = g_gs1[e * 32 + i];
        sQ1[tid] = g_gb1[e * 32 + i];
    }
    if (tid < 128) {
        int ee = tid >> 6, i = tid & 63;
        int e = ee ? e1 : e0;
        sS2[tid] = g_gs2[e * 64 + i];
        sQ2[tid] = g_gb2[e * 64 + i];
    }
    __syncthreads();

    // ---- phase 1: stage XH (once) and both W1H tiles ----
    {
        const float* xb = x + (size_t)b * 3072;
#pragma unroll
        for (int it = 0; it < 4; it++) {
            int pp = tid + it * 256;              // position 0..1023
            float v0 = xb[pp];
            float v1 = xb[1024 + pp];
            float v2 = xb[2048 + pp];
            uint4 u;
            u.x = h2pack(v0, v1);
            u.y = (uint32_t)__half_as_ushort(__float2half_rn(v2));
            u.z = 0; u.w = 0;
            int y = pp >> 5, xx = pp & 31;
            sts128(XHu + (uint32_t)(((y + 1) * 34 + xx + 1) * 16), u);
        }
        const uint4* w1a = (const uint4*)(g_w1h) + (size_t)e0 * 288;
        const uint4* w1b = (const uint4*)(g_w1h) + (size_t)e1 * 288;
        for (int i = tid; i < 576; i += 256) {
            uint4 v = (i < 288) ? w1a[i] : w1b[i - 288];
            sts128(W1Hu + (uint32_t)(i * 16), v);
        }
    }
    __syncthreads();

    // ======== expert loop ========
#pragma unroll 1
    for (int ee = 0; ee < 2; ee++) {
        int e = ee ? e1 : e0;

        // ---- conv1 via fp16 mma (9 taps, m16n8k8), BN+ReLU+pool -> A rows ----
        {
            float s1v[4][2], q1v[4][2];
#pragma unroll
            for (int nt = 0; nt < 4; nt++) {
                int oc0 = nt * 8 + 2 * (lane & 3);
                s1v[nt][0] = sS1[ee * 32 + oc0];     s1v[nt][1] = sS1[ee * 32 + oc0 + 1];
                q1v[nt][0] = sQ1[ee * 32 + oc0];     q1v[nt][1] = sQ1[ee * 32 + oc0 + 1];
            }
            int rr  = (lane & 7) + ((lane >> 3) & 1) * 8;
            int cxA = lane >> 2;
            uint32_t baseB = W1Hu + (uint32_t)(ee * 4608)
                           + (uint32_t)((((lane >> 3) & 3) * 8 + (lane & 7)) * 16);

#pragma unroll
            for (int grp = 0; grp < 2; grp++) {
                int cy = 2 * w + grp;
                float ac[4][4][4];
#pragma unroll
                for (int d = 0; d < 4; d++)
#pragma unroll
                    for (int nt = 0; nt < 4; nt++)
#pragma unroll
                        for (int j = 0; j < 4; j++) ac[d][nt][j] = 0.f;

                uint32_t baseA[2];
#pragma unroll
                for (int pp = 0; pp < 2; pp++) {
                    int d = 2 * pp + (lane >> 4);
                    baseA[pp] = XHu + (uint32_t)((((2 * cy + (d >> 1)) * 34) + 2 * rr + (d & 1)) * 16);
                }

#pragma unroll
                for (int tap = 0; tap < 9; tap++) {
                    uint32_t off = (uint32_t)((((tap / 3) * 34) + (tap % 3)) * 16);
                    uint32_t a0[4], a1[4], bf[4];
                    ldm4(a0, baseA[0] + off);
                    ldm4(a1, baseA[1] + off);
                    ldm4(bf, baseB + (uint32_t)(tap * 512));
#pragma unroll
                    for (int nt = 0; nt < 4; nt++) {
                        mma1688(ac[0][nt], a0[0], a0[1], bf[nt]);
                        mma1688(ac[1][nt], a0[2], a0[3], bf[nt]);
                        mma1688(ac[2][nt], a1[0], a1[1], bf[nt]);
                        mma1688(ac[3][nt], a1[2], a1[3], bf[nt]);
                    }
                }

                int s0 = (cy + 1) * 18 + (cxA + 1);
                int s1 = s0 + 8;
#pragma unroll
                for (int nt = 0; nt < 4; nt++) {
                    float m00 = 0.f, m01 = 0.f, m10 = 0.f, m11 = 0.f;
#pragma unroll
                    for (int d = 0; d < 4; d++) {
                        m00 = fmaxf(m00, fmaxf(0.f, ac[d][nt][0] * s1v[nt][0] + q1v[nt][0]));
                        m01 = fmaxf(m01, fmaxf(0.f, ac[d][nt][1] * s1v[nt][1] + q1v[nt][1]));
                        m10 = fmaxf(m10, fmaxf(0.f, ac[d][nt][2] * s1v[nt][0] + q1v[nt][0]));
                        m11 = fmaxf(m11, fmaxf(0.f, ac[d][nt][3] * s1v[nt][1] + q1v[nt][1]));
                    }
                    int oc0 = nt * 8 + 2 * (lane & 3);
                    sts32(Au + (uint32_t)(s0 * A_STRIDE + 2 * oc0), h2pack(m00, m01));
                    sts32(Au + (uint32_t)(s1 * A_STRIDE + 2 * oc0), h2pack(m10, m11));
                }
            }
        }
        // wait for B2(e) cp.async AND conv1 A stores
        asm volatile("cp.async.wait_group 0;" ::: "memory");
        __syncthreads();

        // ---- conv2 via fp16 mma (9 taps, m16n8k16) ----
        int xl   = lane & 15;
        int colh = lane >> 4;
        uint32_t b_lane = (uint32_t)((((lane >> 4) * 8 + (lane & 7)) * A_STRIDE) + ((lane >> 3) & 1) * 16);

        float acc[2][8][4];
#pragma unroll
        for (int mt = 0; mt < 2; mt++)
#pragma unroll
            for (int nt = 0; nt < 8; nt++)
#pragma unroll
                for (int j = 0; j < 4; j++) acc[mt][nt][j] = 0.f;

#pragma unroll 3
        for (int tap = 0; tap < 9; tap++) {
            uint32_t Bc = B2u + (uint32_t)(tap * 5120);
            int ky = tap / 3, kx = tap % 3;
            uint32_t arow0 = Au + (uint32_t)((((2 * w + ky) * 18) + xl + kx) * A_STRIDE + colh * 16);
            uint32_t arow1 = arow0 + 18 * A_STRIDE;

#pragma unroll
            for (int kc = 0; kc < 2; kc++) {
                uint32_t ko = kc * 32;
                uint32_t a0[4], a1[4];
                ldm4(a0, arow0 + ko);
                ldm4(a1, arow1 + ko);

                uint32_t bf[8][2];
#pragma unroll
                for (int g = 0; g < 4; g++) {
                    uint32_t r[4];
                    ldm4(r, Bc + b_lane + (uint32_t)(g * 16 * A_STRIDE) + ko);
                    bf[g * 2][0] = r[0]; bf[g * 2][1] = r[1];
                    bf[g * 2 + 1][0] = r[2]; bf[g * 2 + 1][1] = r[3];
                }
#pragma unroll
                for (int nt = 0; nt < 8; nt++) {
                    mma16816(acc[0][nt], a0, bf[nt]);
                    mma16816(acc[1][nt], a1, bf[nt]);
                }
            }
        }
        __syncthreads();     // all conv2 reads of B2 done

        // prefetch B2(e1) while pool+fc of e0 run
        if (ee == 0) issue_b2(B2u, e1, tid);

        // ---- BN + ReLU + 2x2 pool (warp-local) -> h2h (fp16) ----
        {
            int c0b  = 2 * (lane & 3);
            bool act = ((lane >> 2) & 1) == 0;
            int pos0 = w * 8 + (lane >> 3);
            int pos1 = pos0 + 4;
#pragma unroll
            for (int nt = 0; nt < 8; nt++) {
                int c0 = nt * 8 + c0b, c1 = c0 + 1;
                float s0 = sS2[ee * 64 + c0], s1 = sS2[ee * 64 + c1];
                float q0 = sQ2[ee * 64 + c0], q1 = sQ2[ee * 64 + c1];
                float v0 = fmaxf(fmaxf(0.f, acc[0][nt][0] * s0 + q0), fmaxf(0.f, acc[1][nt][0] * s0 + q0));
                float v1 = fmaxf(fmaxf(0.f, acc[0][nt][1] * s1 + q1), fmaxf(0.f, acc[1][nt][1] * s1 + q1));
                float v2 = fmaxf(fmaxf(0.f, acc[0][nt][2] * s0 + q0), fmaxf(0.f, acc[1][nt][2] * s0 + q0));
                float v3 = fmaxf(fmaxf(0.f, acc[0][nt][3] * s1 + q1), fmaxf(0.f, acc[1][nt][3] * s1 + q1));
                v0 = fmaxf(v0, __shfl_xor_sync(0xffffffffu, v0, 4));
                v1 = fmaxf(v1, __shfl_xor_sync(0xffffffffu, v1, 4));
                v2 = fmaxf(v2, __shfl_xor_sync(0xffffffffu, v2, 4));
                v3 = fmaxf(v3, __shfl_xor_sync(0xffffffffu, v3, 4));
                if (act) {
                    h2h[c0 * 64 + pos0] = __float2half_rn(v0);
                    h2h[c1 * 64 + pos0] = __float2half_rn(v1);
                    h2h[c0 * 64 + pos1] = __float2half_rn(v2);
                    h2h[c1 * 64 + pos1] = __float2half_rn(v3);
                }
            }
        }
        __syncthreads();

        // ---- coalesced fc GEMV, fp16 weights x fp16 h2 ----
        const uint4* feh  = (const uint4*)(g_fcwh) + (size_t)e * 5120;
        const uint4* h2v  = (const uint4*)(sb + H2S_OFF);   // 8 halfs per uint4
        float fca[10];
#pragma unroll
        for (int o = 0; o < 10; o++) fca[o] = 0.f;
#pragma unroll
        for (int it = 0; it < 2; it++) {
            int j8 = it * 256 + tid;                  // 8-elem stripe 0..511
            uint4 hv = h2v[j8];
            float2 h0 = __half22float2(*(const __half2*)&hv.x);
            float2 h1 = __half22float2(*(const __half2*)&hv.y);
            float2 h2_ = __half22float2(*(const __half2*)&hv.z);
            float2 h3 = __half22float2(*(const __half2*)&hv.w);
#pragma unroll
            for (int o = 0; o < 10; o++) {
                uint4 wv = feh[o * 512 + j8];
                float2 w0 = __half22float2(*(const __half2*)&wv.x);
                float2 w1 = __half22float2(*(const __half2*)&wv.y);
                float2 w2v = __half22float2(*(const __half2*)&wv.z);
                float2 w3 = __half22float2(*(const __half2*)&wv.w);
                fca[o] += h0.x * w0.x + h0.y * w0.y + h1.x * w1.x + h1.y * w1.y
                        + h2_.x * w2v.x + h2_.y * w2v.y + h3.x * w3.x + h3.y * w3.y;
            }
        }

        // ---- reduce fc partials -> oo[ee] ----
#pragma unroll
        for (int o = 0; o < 10; o++)
#pragma unroll
            for (int off = 16; off; off >>= 1)
                fca[o] += __shfl_xor_sync(0xffffffffu, fca[o], off);
        if (lane == 0)
#pragma unroll
            for (int o = 0; o < 10; o++) redm[w * 10 + o] = fca[o];
        __syncthreads();
        if (tid < 10) {
            float s = 0.f;
#pragma unroll
            for (int ww = 0; ww < 8; ww++) s += redm[ww * 10 + tid];
            oo[ee * 10 + tid] = s + fcb[e * 10 + tid];
        }
        __syncthreads();
    }

    // ---- final combine: y = log(g0*exp(o0) + g1*exp(o1)) ----
    if (tid < 10) {
        float g0 = g_gatev[2 * b], g1 = g_gatev[2 * b + 1];
        float c = g0 * expf(oo[tid]) + g1 * expf(oo[10 + tid]);
        if (c == 0.f) c = 2.2204460492503131e-16f;   // np.finfo(float).eps
        out[b * 10 + tid] = logf(c);
    }
}

// ---------------- loss: CV^2(importance) + CV^2(load), deterministic ----------------
__global__ void loss_kernel(float* __restrict__ out, int out_size) {
    __shared__ float rimp[8 * 8];
    __shared__ float rcnt[8 * 8];
    int t = threadIdx.x;   // 256
    float imp[8], cnt[8];
#pragma unroll
    for (int i = 0; i < 8; i++) { imp[i] = 0.f; cnt[i] = 0.f; }
    for (int p = t; p < 2 * BATCH; p += 256) {
        int e = g_expid[p];
        imp[e] += g_gatev[p];
        cnt[e] += 1.f;
    }
#pragma unroll
    for (int off = 16; off; off >>= 1)
#pragma unroll
        for (int i = 0; i < 8; i++) {
            imp[i] += __shfl_xor_sync(0xffffffffu, imp[i], off);
            cnt[i] += __shfl_xor_sync(0xffffffffu, cnt[i], off);
        }
    if ((t & 31) == 0)
#pragma unroll
        for (int i = 0; i < 8; i++) {
            rimp[(t >> 5) * 8 + i] = imp[i];
            rcnt[(t >> 5) * 8 + i] = cnt[i];
        }
    __syncthreads();
    if (t == 0) {
        double si = 0, sl = 0, si2 = 0, sl2 = 0;
        for (int e = 0; e < 8; e++) {
            double vi = 0, vl = 0;
            for (int w = 0; w < 8; w++) { vi += rimp[w * 8 + e]; vl += rcnt[w * 8 + e]; }
            si += vi; sl += vl; si2 += vi * vi; sl2 += vl * vl;
        }
        double mi = si / 8.0, ml = sl / 8.0;
        double vari = (si2 - 8.0 * mi * mi) / 7.0;   // ddof=1
        double varl = (sl2 - 8.0 * ml * ml) / 7.0;
        double loss = (vari / (mi * mi + 1e-10) + varl / (ml * ml + 1e-10)) * 0.01;
        out[out_size - 1] = (float)loss;
    }
}

// ---------------- launch ----------------
extern "C" void kernel_launch(void* const* d_in, const int* in_sizes, int n_in,
                              void* d_out, int out_size) {
    const float* x   = (const float*)d_in[0];
    // d_in[1] = index (unused by reference math)
    const float* wg  = (const float*)d_in[2];
    const float* w1  = (const float*)d_in[3];
    const float* b1  = (const float*)d_in[4];
    const float* g1  = (const float*)d_in[5];
    const float* be1 = (const float*)d_in[6];
    const float* rm1 = (const float*)d_in[7];
    const float* rv1 = (const float*)d_in[8];
    const float* w2  = (const float*)d_in[9];
    const float* b2  = (const float*)d_in[10];
    const float* g2  = (const float*)d_in[11];
    const float* be2 = (const float*)d_in[12];
    const float* rm2 = (const float*)d_in[13];
    const float* rv2 = (const float*)d_in[14];
    const float* fcw = (const float*)d_in[15];
    const float* fcb = (const float*)d_in[16];
    float* out = (float*)d_out;

    cudaFuncSetAttribute(sample_kernel, cudaFuncAttributeMaxDynamicSharedMemorySize, SMEM_BYTES);

    prep_kernel<<<1280, 256>>>(w1, w2, fcw, b1, g1, be1, rm1, rv1, b2, g2, be2, rm2, rv2);
    gate_kernel<<<BATCH / GS, 256>>>(x, wg);
    sample_kernel<<<BATCH, 256, SMEM_BYTES>>>(x, fcb, out);
    loss_kernel<<<1, 256>>>(out, out_size);
}

// round 17
// speedup vs baseline: 1.0750x; 1.0750x over previous
#include <cuda_runtime.h>
#include <cuda_fp16.h>
#include <cstdint>

#define NEXP  8
#define BATCH 4096
#define GS    4

// ---------------- device scratch (no allocations allowed) ----------------
__device__ float g_gs1[NEXP * 32];
__device__ float g_gb1[NEXP * 32];
__device__ float g_gs2[NEXP * 64];
__device__ float g_gb2[NEXP * 64];
__device__ int   g_expid[2 * BATCH];
__device__ float g_gatev[2 * BATCH];
__device__ float g_pout[2 * BATCH * 10];
// W2 fp16 pre-padded to smem row layout: [e][tap][oc64][ic0..31 + 8 pad halfs] (pad stays 0)
__device__ __half g_w2s[NEXP * 9 * 64 * 40];
// W1 in fp16, tap-major: [e][tap][oc32][k8: ic0..2, 0...]  (zero-padded; .bss zero-init)
__device__ __half g_w1h[NEXP * 9 * 32 * 8];
// fc weights in fp16: [e][o10][j4096]
__device__ __half g_fcwh[NEXP * 10 * 4096];

// ---------------- smem / mma helpers ----------------
static __device__ __forceinline__ uint32_t smem_u32(const void* p) {
    uint32_t a;
    asm("{ .reg .u64 t; cvta.to.shared.u64 t, %1; cvt.u32.u64 %0, t; }" : "=r"(a) : "l"(p));
    return a;
}
static __device__ __forceinline__ void sts32(uint32_t a, uint32_t v) {
    asm volatile("st.shared.b32 [%0], %1;" :: "r"(a), "r"(v) : "memory");
}
static __device__ __forceinline__ void sts128(uint32_t a, uint4 v) {
    asm volatile("st.shared.v4.b32 [%0], {%1,%2,%3,%4};" :: "r"(a), "r"(v.x), "r"(v.y), "r"(v.z), "r"(v.w) : "memory");
}
static __device__ __forceinline__ void cpa16(uint32_t smem, const void* gmem) {
    asm volatile("cp.async.cg.shared.global [%0], [%1], 16;" :: "r"(smem), "l"(gmem) : "memory");
}
static __device__ __forceinline__ void ldm4(uint32_t* r, uint32_t addr) {
    asm volatile("ldmatrix.sync.aligned.m8n8.x4.shared.b16 {%0,%1,%2,%3}, [%4];"
                 : "=r"(r[0]), "=r"(r[1]), "=r"(r[2]), "=r"(r[3]) : "r"(addr));
}
static __device__ __forceinline__ void mma16816(float* d, const uint32_t* a, const uint32_t* b) {
    asm volatile("mma.sync.aligned.m16n8k16.row.col.f32.f16.f16.f32 "
                 "{%0,%1,%2,%3}, {%4,%5,%6,%7}, {%8,%9}, {%0,%1,%2,%3};"
                 : "+f"(d[0]), "+f"(d[1]), "+f"(d[2]), "+f"(d[3])
                 : "r"(a[0]), "r"(a[1]), "r"(a[2]), "r"(a[3]), "r"(b[0]), "r"(b[1]));
}
static __device__ __forceinline__ void mma1688(float* d, uint32_t a0, uint32_t a1, uint32_t b0) {
    asm volatile("mma.sync.aligned.m16n8k8.row.col.f32.f16.f16.f32 "
                 "{%0,%1,%2,%3}, {%4,%5}, {%6}, {%0,%1,%2,%3};"
                 : "+f"(d[0]), "+f"(d[1]), "+f"(d[2]), "+f"(d[3])
                 : "r"(a0), "r"(a1), "r"(b0));
}
static __device__ __forceinline__ uint32_t h2pack(float a, float b) {
    return ((uint32_t)__half_as_ushort(__float2half_rn(b)) << 16)
         | (uint32_t)__half_as_ushort(__float2half_rn(a));
}

// ---------------- fused prep: BN fold + W1/W2/fcw fp16 conversion ----------------
__global__ void prep_kernel(const float* __restrict__ w1, const float* __restrict__ w2,
                            const float* __restrict__ fcw,
                            const float* __restrict__ b1, const float* __restrict__ g1,
                            const float* __restrict__ be1, const float* __restrict__ rm1,
                            const float* __restrict__ rv1,
                            const float* __restrict__ b2, const float* __restrict__ g2,
                            const float* __restrict__ be2, const float* __restrict__ rm2,
                            const float* __restrict__ rv2) {
    int idx = blockIdx.x * 256 + threadIdx.x;
    if (idx < NEXP * 32) {
        float s = g1[idx] / sqrtf(rv1[idx] + 1e-5f);
        g_gs1[idx] = s;
        g_gb1[idx] = (b1[idx] - rm1[idx]) * s + be1[idx];
    }
    if (idx < NEXP * 64) {
        float s = g2[idx] / sqrtf(rv2[idx] + 1e-5f);
        g_gs2[idx] = s;
        g_gb2[idx] = (b2[idx] - rm2[idx]) * s + be2[idx];
    }
    if (idx < NEXP * 9 * 32 * 3) {
        int ic  = idx % 3;
        int t   = idx / 3;
        int oc  = t % 32;  t /= 32;
        int tap = t % 9;
        int e   = t / 9;
        float v = w1[(((size_t)e * 32 + oc) * 3 + ic) * 9 + tap];
        g_w1h[((size_t)(e * 9 + tap) * 32 + oc) * 8 + ic] = __float2half_rn(v);
    }
    if (idx < NEXP * 9 * 64 * 32) {
        int ic  = idx & 31;
        int oc  = (idx >> 5) & 63;
        int r   = idx >> 11;
        int tap = r % 9;
        int e   = r / 9;
        float w = w2[(((size_t)e * 64 + oc) * 32 + ic) * 9 + tap];
        g_w2s[((size_t)(e * 9 + tap) * 64 + oc) * 40 + ic] = __float2half_rn(w);
    }
    if (idx < NEXP * 10 * 4096) {
        g_fcwh[idx] = __float2half_rn(fcw[idx]);
    }
}

// ---------------- gating: 4 samples per block, float4 both sides ----------------
__global__ void __launch_bounds__(256) gate_kernel(const float* __restrict__ x,
                                                   const float* __restrict__ wg) {
    __shared__ float red[8][GS * 8];
    int b0 = blockIdx.x * GS;
    int t  = threadIdx.x;            // 256 threads
    int lane = t & 31, w = t >> 5;
    const float4* xb4 = (const float4*)(x + (size_t)b0 * 3072);

    float p[GS][8];
#pragma unroll
    for (int s = 0; s < GS; s++)
#pragma unroll
        for (int i = 0; i < 8; i++) p[s][i] = 0.f;

#pragma unroll
    for (int it = 0; it < 3; it++) {
        int j4 = t + it * 256;       // float4 index 0..767
        const float4* w4 = (const float4*)(wg + (size_t)j4 * 32);
        float4 xv[GS];
#pragma unroll
        for (int s = 0; s < GS; s++) xv[s] = xb4[s * 768 + j4];
#pragma unroll
        for (int k = 0; k < 4; k++) {
            float4 w0 = w4[2 * k], w1 = w4[2 * k + 1];
#pragma unroll
            for (int s = 0; s < GS; s++) {
                float xk = (k == 0) ? xv[s].x : (k == 1) ? xv[s].y : (k == 2) ? xv[s].z : xv[s].w;
                p[s][0] += xk * w0.x; p[s][1] += xk * w0.y; p[s][2] += xk * w0.z; p[s][3] += xk * w0.w;
                p[s][4] += xk * w1.x; p[s][5] += xk * w1.y; p[s][6] += xk * w1.z; p[s][7] += xk * w1.w;
            }
        }
    }
#pragma unroll
    for (int off = 16; off; off >>= 1)
#pragma unroll
        for (int s = 0; s < GS; s++)
#pragma unroll
            for (int i = 0; i < 8; i++) p[s][i] += __shfl_xor_sync(0xffffffffu, p[s][i], off);
    if (lane == 0)
#pragma unroll
        for (int s = 0; s < GS; s++)
#pragma unroll
            for (int i = 0; i < 8; i++) red[w][s * 8 + i] = p[s][i];
    __syncthreads();
    if (t < GS * 8) {
        float sum = 0.f;
#pragma unroll
        for (int ww = 0; ww < 8; ww++) sum += red[ww][t];
        red[0][t] = sum;
    }
    __syncthreads();
    if (t < GS) {
        float lg[8];
#pragma unroll
        for (int i = 0; i < 8; i++) lg[i] = red[0][t * 8 + i];
        // top-2, first-occurrence tie order (matches jax.lax.top_k)
        int i0 = 0;
#pragma unroll
        for (int e = 1; e < 8; e++) if (lg[e] > lg[i0]) i0 = e;
        int i1 = -1;
#pragma unroll
        for (int e = 0; e < 8; e++) {
            if (e == i0) continue;
            if (i1 < 0 || lg[e] > lg[i1]) i1 = e;
        }
        float t1  = expf(lg[i1] - lg[i0]);     // <= 1
        float inv = 1.f / (1.f + t1);
        int b = b0 + t;
        g_expid[2 * b]     = i0;
        g_gatev[2 * b]     = inv;
        g_expid[2 * b + 1] = i1;
        g_gatev[2 * b + 1] = t1 * inv;
    }
}

// ---------------- fused expert kernel (256 thr): fp16 mma convs, cp.async B2 ----------------
// smem layout (bytes):
//  A    [0, 25920):       324 rows x 80B (conv2 A: [s][32 oc fp16] + 16B pad)
//                         reused after phase 3 as h2s[4096] f32 (16KB)
//  B2   [25920, 72000):   9 taps x 64 rows x 80B (conv2 weights, cp.async-staged)
//  XH   [72000, 90496):   conv1 input fp16, 34x34 grid x 16B rows [ic0..2, 0pad]
//  W1H  [90496, 95104):   9 taps x 32 rows x 16B (conv1 weights)
//  sS1  [95104,+128) sQ1 [95232,+128) sS2 [95360,+256) sQ2 [95616,+256) red [95872,+320)
#define A_STRIDE 80
#define B2_OFF   25920
#define XH_OFF   72000
#define W1H_OFF  90496
#define SS1_OFF  95104
#define SQ1_OFF  95232
#define SS2_OFF  95360
#define SQ2_OFF  95616
#define RED_OFF  95872
#define SMEM_BYTES (RED_OFF + 320)

__global__ void __launch_bounds__(256, 2) pair_kernel(
    const float* __restrict__ x, const float* __restrict__ fcb) {
    extern __shared__ __align__(128) char sb[];
    uint32_t Au   = smem_u32(sb);
    uint32_t B2u  = Au + B2_OFF;
    uint32_t XHu  = Au + XH_OFF;
    uint32_t W1Hu = Au + W1H_OFF;
    float* sS1  = (float*)(sb + SS1_OFF);
    float* sQ1  = (float*)(sb + SQ1_OFF);
    float* sS2  = (float*)(sb + SS2_OFF);
    float* sQ2  = (float*)(sb + SQ2_OFF);
    float* redm = (float*)(sb + RED_OFF);
    float* h2s  = (float*)sb;                     // overlays A after phase 3

    int p    = blockIdx.x;
    int b    = p >> 1;
    int e    = g_expid[p];
    int tid  = threadIdx.x;
    int lane = tid & 31;
    int w    = tid >> 5;

    // ---- issue cp.async for all 9 B2 tap tiles (waited before phase 3) ----
    {
        const uint4* w2src = (const uint4*)(g_w2s) + (size_t)e * 2880;  // 46080 B
#pragma unroll
        for (int j = 0; j < 11; j++) {
            int i = tid + j * 256;
            cpa16(B2u + (uint32_t)(i * 16), w2src + i);
        }
        {
            int i = tid + 11 * 256;
            if (i < 2880) cpa16(B2u + (uint32_t)(i * 16), w2src + i);
        }
        asm volatile("cp.async.commit_group;" ::: "memory");
    }

    // ---- phase 0: zero A halo + XH; load BN consts ----
    for (int i = tid; i < 1620; i += 256) sts128(Au + i * 16, make_uint4(0, 0, 0, 0));
    for (int i = tid; i < 1156; i += 256) sts128(XHu + i * 16, make_uint4(0, 0, 0, 0));
    if (tid < 32) {
        sS1[tid] = g_gs1[e * 32 + tid];
        sQ1[tid] = g_gb1[e * 32 + tid];
    }
    if (tid < 64) {
        sS2[tid] = g_gs2[e * 64 + tid];
        sQ2[tid] = g_gb2[e * 64 + tid];
    }
    __syncthreads();

    // ---- phase 1: stage XH interior (x->fp16) and W1H ----
    {
        const float* xb = x + (size_t)b * 3072;
#pragma unroll
        for (int it = 0; it < 4; it++) {
            int pp = tid + it * 256;              // position 0..1023
            float v0 = xb[pp];
            float v1 = xb[1024 + pp];
            float v2 = xb[2048 + pp];
            uint4 u;
            u.x = h2pack(v0, v1);
            u.y = (uint32_t)__half_as_ushort(__float2half_rn(v2));
            u.z = 0; u.w = 0;
            int y = pp >> 5, xx = pp & 31;
            sts128(XHu + (uint32_t)(((y + 1) * 34 + xx + 1) * 16), u);
        }
        const uint4* w1src = (const uint4*)(g_w1h) + (size_t)e * 9 * 32;   // 288 uint4
        for (int i = tid; i < 288; i += 256)
            sts128(W1Hu + (uint32_t)(i * 16), w1src[i]);
    }
    __syncthreads();

    // ---- phase 2: conv1 via fp16 mma (9 taps, m16n8k8), BN+ReLU+pool -> A rows ----
    {
        float s1v[4][2], q1v[4][2];
#pragma unroll
        for (int nt = 0; nt < 4; nt++) {
            int oc0 = nt * 8 + 2 * (lane & 3);
            s1v[nt][0] = sS1[oc0];     s1v[nt][1] = sS1[oc0 + 1];
            q1v[nt][0] = sQ1[oc0];     q1v[nt][1] = sQ1[oc0 + 1];
        }
        int rr  = (lane & 7) + ((lane >> 3) & 1) * 8;   // ldmatrix row within tile
        int cxA = lane >> 2;                            // c-frag row
        uint32_t baseB = W1Hu + (uint32_t)((((lane >> 3) & 3) * 8 + (lane & 7)) * 16);

#pragma unroll
        for (int grp = 0; grp < 2; grp++) {
            int cy = 2 * w + grp;                       // pooled row
            float ac[4][4][4];
#pragma unroll
            for (int d = 0; d < 4; d++)
#pragma unroll
                for (int nt = 0; nt < 4; nt++)
#pragma unroll
                    for (int j = 0; j < 4; j++) ac[d][nt][j] = 0.f;

            uint32_t baseA[2];
#pragma unroll
            for (int pp = 0; pp < 2; pp++) {
                int d = 2 * pp + (lane >> 4);
                baseA[pp] = XHu + (uint32_t)((((2 * cy + (d >> 1)) * 34) + 2 * rr + (d & 1)) * 16);
            }

#pragma unroll
            for (int tap = 0; tap < 9; tap++) {
                uint32_t off = (uint32_t)((((tap / 3) * 34) + (tap % 3)) * 16);
                uint32_t a0[4], a1[4], bf[4];
                ldm4(a0, baseA[0] + off);               // d-tiles 0,1
                ldm4(a1, baseA[1] + off);               // d-tiles 2,3
                ldm4(bf, baseB + (uint32_t)(tap * 512));
#pragma unroll
                for (int nt = 0; nt < 4; nt++) {
                    mma1688(ac[0][nt], a0[0], a0[1], bf[nt]);
                    mma1688(ac[1][nt], a0[2], a0[3], bf[nt]);
                    mma1688(ac[2][nt], a1[0], a1[1], bf[nt]);
                    mma1688(ac[3][nt], a1[2], a1[3], bf[nt]);
                }
            }

            // epilogue: pool over d in-register, BN+ReLU, store fp16 A rows
            int s0 = (cy + 1) * 18 + (cxA + 1);
            int s1 = s0 + 8;
#pragma unroll
            for (int nt = 0; nt < 4; nt++) {
                float m00 = 0.f, m01 = 0.f, m10 = 0.f, m11 = 0.f;
#pragma unroll
                for (int d = 0; d < 4; d++) {
                    m00 = fmaxf(m00, fmaxf(0.f, ac[d][nt][0] * s1v[nt][0] + q1v[nt][0]));
                    m01 = fmaxf(m01, fmaxf(0.f, ac[d][nt][1] * s1v[nt][1] + q1v[nt][1]));
                    m10 = fmaxf(m10, fmaxf(0.f, ac[d][nt][2] * s1v[nt][0] + q1v[nt][0]));
                    m11 = fmaxf(m11, fmaxf(0.f, ac[d][nt][3] * s1v[nt][1] + q1v[nt][1]));
                }
                int oc0 = nt * 8 + 2 * (lane & 3);
                sts32(Au + (uint32_t)(s0 * A_STRIDE + 2 * oc0), h2pack(m00, m01));
                sts32(Au + (uint32_t)(s1 * A_STRIDE + 2 * oc0), h2pack(m10, m11));
            }
        }
    }
    // wait for B2 cp.async AND conv1 A stores before conv2
    asm volatile("cp.async.wait_group 0;" ::: "memory");
    __syncthreads();

    // ---- phase 3: conv2 via fp16 mma (9 taps, m16n8k16), unroll for ILP ----
    int xl   = lane & 15;
    int colh = lane >> 4;
    uint32_t b_lane = (uint32_t)((((lane >> 4) * 8 + (lane & 7)) * A_STRIDE) + ((lane >> 3) & 1) * 16);

    float acc[2][8][4];
#pragma unroll
    for (int mt = 0; mt < 2; mt++)
#pragma unroll
        for (int nt = 0; nt < 8; nt++)
#pragma unroll
            for (int j = 0; j < 4; j++) acc[mt][nt][j] = 0.f;

#pragma unroll 3
    for (int tap = 0; tap < 9; tap++) {
        uint32_t Bc = B2u + (uint32_t)(tap * 5120);
        int ky = tap / 3, kx = tap % 3;
        uint32_t arow0 = Au + (uint32_t)((((2 * w + ky) * 18) + xl + kx) * A_STRIDE + colh * 16);
        uint32_t arow1 = arow0 + 18 * A_STRIDE;

#pragma unroll
        for (int kc = 0; kc < 2; kc++) {
            uint32_t ko = kc * 32;
            uint32_t a0[4], a1[4];
            ldm4(a0, arow0 + ko);
            ldm4(a1, arow1 + ko);

            uint32_t bf[8][2];
#pragma unroll
            for (int g = 0; g < 4; g++) {
                uint32_t r[4];
                ldm4(r, Bc + b_lane + (uint32_t)(g * 16 * A_STRIDE) + ko);
                bf[g * 2][0] = r[0]; bf[g * 2][1] = r[1];
                bf[g * 2 + 1][0] = r[2]; bf[g * 2 + 1][1] = r[3];
            }
#pragma unroll
            for (int nt = 0; nt < 8; nt++) {
                mma16816(acc[0][nt], a0, bf[nt]);
                mma16816(acc[1][nt], a1, bf[nt]);
            }
        }
    }
    __syncthreads();

    // ---- phase 4: BN + ReLU + 2x2 pool (warp-local) -> h2s smem ----
    {
        int c0b  = 2 * (lane & 3);
        bool act = ((lane >> 2) & 1) == 0;
        int pos0 = w * 8 + (lane >> 3);       // pooled flat pos (py=w, px=lane>>3)
        int pos1 = pos0 + 4;
#pragma unroll
        for (int nt = 0; nt < 8; nt++) {
            int c0 = nt * 8 + c0b, c1 = c0 + 1;
            float s0 = sS2[c0], s1 = sS2[c1], q0 = sQ2[c0], q1 = sQ2[c1];
            float v0 = fmaxf(fmaxf(0.f, acc[0][nt][0] * s0 + q0), fmaxf(0.f, acc[1][nt][0] * s0 + q0));
            float v1 = fmaxf(fmaxf(0.f, acc[0][nt][1] * s1 + q1), fmaxf(0.f, acc[1][nt][1] * s1 + q1));
            float v2 = fmaxf(fmaxf(0.f, acc[0][nt][2] * s0 + q0), fmaxf(0.f, acc[1][nt][2] * s0 + q0));
            float v3 = fmaxf(fmaxf(0.f, acc[0][nt][3] * s1 + q1), fmaxf(0.f, acc[1][nt][3] * s1 + q1));
            v0 = fmaxf(v0, __shfl_xor_sync(0xffffffffu, v0, 4));
            v1 = fmaxf(v1, __shfl_xor_sync(0xffffffffu, v1, 4));
            v2 = fmaxf(v2, __shfl_xor_sync(0xffffffffu, v2, 4));
            v3 = fmaxf(v3, __shfl_xor_sync(0xffffffffu, v3, 4));
            if (act) {
                h2s[c0 * 64 + pos0] = v0;
                h2s[c1 * 64 + pos0] = v1;
                h2s[c0 * 64 + pos1] = v2;
                h2s[c1 * 64 + pos1] = v3;
            }
        }
    }
    __syncthreads();

    // ---- phase 5: coalesced fc GEMV with fp16 weights ----
    const uint4* feh = (const uint4*)(g_fcwh) + (size_t)e * 5120;   // 10 x 512 uint4
    const float4* h2s4 = (const float4*)h2s;
    float fca[10];
#pragma unroll
    for (int o = 0; o < 10; o++) fca[o] = 0.f;
#pragma unroll
    for (int it = 0; it < 2; it++) {
        int j8 = it * 256 + tid;                  // 8-float stripe index 0..511
        float4 ha = h2s4[2 * j8];
        float4 hb = h2s4[2 * j8 + 1];
#pragma unroll
        for (int o = 0; o < 10; o++) {
            uint4 wv = feh[o * 512 + j8];
            float2 w0 = __half22float2(*(const __half2*)&wv.x);
            float2 w1 = __half22float2(*(const __half2*)&wv.y);
            float2 w2v = __half22float2(*(const __half2*)&wv.z);
            float2 w3 = __half22float2(*(const __half2*)&wv.w);
            fca[o] += ha.x * w0.x + ha.y * w0.y + ha.z * w1.x + ha.w * w1.y
                    + hb.x * w2v.x + hb.y * w2v.y + hb.z * w3.x + hb.w * w3.y;
        }
    }

    // ---- phase 6: reduce fc partials, write pair output ----
#pragma unroll
    for (int o = 0; o < 10; o++)
#pragma unroll
        for (int off = 16; off; off >>= 1)
            fca[o] += __shfl_xor_sync(0xffffffffu, fca[o], off);

    if (lane == 0)
#pragma unroll
        for (int o = 0; o < 10; o++) redm[w * 10 + o] = fca[o];
    __syncthreads();
    if (tid < 10) {
        float s = 0.f;
#pragma unroll
        for (int ww = 0; ww < 8; ww++) s += redm[ww * 10 + tid];
        g_pout[p * 10 + tid] = s + fcb[e * 10 + tid];
    }
}

// ---------------- combine: y = log(g0*exp(o0) + g1*exp(o1)) ----------------
__global__ void combine_kernel(float* __restrict__ out) {
    int idx = blockIdx.x * blockDim.x + threadIdx.x;
    if (idx >= BATCH * 10) return;
    int b = idx / 10, o = idx - b * 10;
    float g0 = g_gatev[2 * b], g1 = g_gatev[2 * b + 1];
    float c = g0 * expf(g_pout[(2 * b) * 10 + o]) + g1 * expf(g_pout[(2 * b + 1) * 10 + o]);
    if (c == 0.f) c = 2.2204460492503131e-16f;   // np.finfo(float).eps
    out[idx] = logf(c);
}

// ---------------- loss: CV^2(importance) + CV^2(load), 1024 threads, MLP 8 ----------------
__global__ void __launch_bounds__(1024) loss_kernel(float* __restrict__ out, int out_size) {
    __shared__ float rimp[32][8];
    __shared__ float rcnt[32][8];
    int t = threadIdx.x;   // 1024
    int lane = t & 31, w = t >> 5;
    float imp[8], cnt[8];
#pragma unroll
    for (int i = 0; i < 8; i++) { imp[i] = 0.f; cnt[i] = 0.f; }
#pragma unroll
    for (int i = 0; i < 8; i++) {
        int p = t + i * 1024;        // 8192 pairs total, coalesced
        int e = g_expid[p];
        float g = g_gatev[p];
        imp[e] += g;
        cnt[e] += 1.f;
    }
#pragma unroll
    for (int off = 16; off; off >>= 1)
#pragma unroll
        for (int i = 0; i < 8; i++) {
            imp[i] += __shfl_xor_sync(0xffffffffu, imp[i], off);
            cnt[i] += __shfl_xor_sync(0xffffffffu, cnt[i], off);
        }
    if (lane == 0)
#pragma unroll
        for (int i = 0; i < 8; i++) {
            rimp[w][i] = imp[i];
            rcnt[w][i] = cnt[i];
        }
    __syncthreads();
    if (t == 0) {
        double si = 0, sl = 0, si2 = 0, sl2 = 0;
        for (int e = 0; e < 8; e++) {
            double vi = 0, vl = 0;
            for (int ww = 0; ww < 32; ww++) { vi += rimp[ww][e]; vl += rcnt[ww][e]; }
            si += vi; sl += vl; si2 += vi * vi; sl2 += vl * vl;
        }
        double mi = si / 8.0, ml = sl / 8.0;
        double vari = (si2 - 8.0 * mi * mi) / 7.0;   // ddof=1
        double varl = (sl2 - 8.0 * ml * ml) / 7.0;
        double loss = (vari / (mi * mi + 1e-10) + varl / (ml * ml + 1e-10)) * 0.01;
        out[out_size - 1] = (float)loss;
    }
}

// ---------------- launch ----------------
extern "C" void kernel_launch(void* const* d_in, const int* in_sizes, int n_in,
                              void* d_out, int out_size) {
    const float* x   = (const float*)d_in[0];
    // d_in[1] = index (unused by reference math)
    const float* wg  = (const float*)d_in[2];
    const float* w1  = (const float*)d_in[3];
    const float* b1  = (const float*)d_in[4];
    const float* g1  = (const float*)d_in[5];
    const float* be1 = (const float*)d_in[6];
    const float* rm1 = (const float*)d_in[7];
    const float* rv1 = (const float*)d_in[8];
    const float* w2  = (const float*)d_in[9];
    const float* b2  = (const float*)d_in[10];
    const float* g2  = (const float*)d_in[11];
    const float* be2 = (const float*)d_in[12];
    const float* rm2 = (const float*)d_in[13];
    const float* rv2 = (const float*)d_in[14];
    const float* fcw = (const float*)d_in[15];
    const float* fcb = (const float*)d_in[16];
    float* out = (float*)d_out;

    cudaFuncSetAttribute(pair_kernel, cudaFuncAttributeMaxDynamicSharedMemorySize, SMEM_BYTES);

    prep_kernel<<<1280, 256>>>(w1, w2, fcw, b1, g1, be1, rm1, rv1, b2, g2, be2, rm2, rv2);
    gate_kernel<<<BATCH / GS, 256>>>(x, wg);
    pair_kernel<<<2 * BATCH, 256, SMEM_BYTES>>>(x, fcb);
    combine_kernel<<<(BATCH * 10 + 255) / 256, 256>>>(out);
    loss_kernel<<<1, 1024>>>(out, out_size);
}